// round 2
// baseline (speedup 1.0000x reference)
#include <cuda_runtime.h>
#include <cuda_bf16.h>
#include <cstdint>

// ============================================================================
// ContrastiveLoss: N=16384, D=256, T=0.07
// loss = mean_i [ log(sum_j exp((c_ij - 1)/T)) + (1 - selfdot_i)/T ]
// c_ij = <q_i, q_j>, q = bf16-quantized L2-normalized rows.
// Base sm_103 ISA only: mma.sync (HMMA) + ldmatrix + cp.async. No tcgen05.
// ============================================================================

#define N_ROWS 16384
#define DIM    256
#define TILE   128
#define NT     (N_ROWS / TILE)   // 128
#define THREADS 256

#define INV_T      14.285714285714286f
#define EX2_SCALE  20.60992915555662f   // log2(e)/0.07

__device__ __nv_bfloat16 g_embn[N_ROWS * DIM];   // normalized bf16 rows, row-major (512B/row)
__device__ float g_selfdot[N_ROWS];
__device__ float g_partial[NT];

// ---------------------------------------------------------------------------
// helpers
// ---------------------------------------------------------------------------
__device__ __forceinline__ uint32_t smem_u32(const void* p) {
    uint32_t a;
    asm("{ .reg .u64 t; cvta.to.shared.u64 t, %1; cvt.u32.u64 %0, t; }" : "=r"(a) : "l"(p));
    return a;
}

__device__ __forceinline__ float ex2f(float x) {
    float y;
    asm("ex2.approx.ftz.f32 %0, %1;" : "=f"(y) : "f"(x));
    return y;
}

// swizzled 16B-unit column within a 512B row: conflict-free for ldmatrix
#define SWZ16(row, c16) (((((c16) ^ (row)) & 7) | ((c16) & 24)))

__device__ __forceinline__ void lm4(uint32_t addr, uint32_t r[4]) {
    asm volatile("ldmatrix.sync.aligned.m8n8.x4.shared.b16 {%0,%1,%2,%3}, [%4];"
                 : "=r"(r[0]), "=r"(r[1]), "=r"(r[2]), "=r"(r[3]) : "r"(addr));
}

__device__ __forceinline__ void mma16816(float c[4], const uint32_t a[4],
                                         uint32_t b0, uint32_t b1) {
    asm volatile(
        "mma.sync.aligned.m16n8k16.row.col.f32.bf16.bf16.f32 "
        "{%0,%1,%2,%3}, {%4,%5,%6,%7}, {%8,%9}, {%0,%1,%2,%3};"
        : "+f"(c[0]), "+f"(c[1]), "+f"(c[2]), "+f"(c[3])
        : "r"(a[0]), "r"(a[1]), "r"(a[2]), "r"(a[3]), "r"(b0), "r"(b1));
}

__device__ __forceinline__ void cp_async16(uint32_t dst, uint64_t src) {
    asm volatile("cp.async.cg.shared.global [%0], [%1], 16;" :: "r"(dst), "l"(src) : "memory");
}
__device__ __forceinline__ void cp_commit() {
    asm volatile("cp.async.commit_group;" ::: "memory");
}

// ---------------------------------------------------------------------------
// Kernel 1: normalize rows -> bf16, plus self-dot of quantized row
// ---------------------------------------------------------------------------
__global__ void __launch_bounds__(256) normalize_kernel(const float* __restrict__ in) {
    int row  = blockIdx.x * 8 + (threadIdx.x >> 5);
    int lane = threadIdx.x & 31;

    const float4* p = reinterpret_cast<const float4*>(in + (size_t)row * DIM);
    float4 a = p[lane];
    float4 b = p[lane + 32];

    float s = a.x*a.x + a.y*a.y + a.z*a.z + a.w*a.w
            + b.x*b.x + b.y*b.y + b.z*b.z + b.w*b.w;
    #pragma unroll
    for (int o = 16; o; o >>= 1) s += __shfl_xor_sync(0xffffffffu, s, o);

    float inv = 1.0f / sqrtf(s);

    __nv_bfloat16 q[8];
    q[0] = __float2bfloat16(a.x * inv); q[1] = __float2bfloat16(a.y * inv);
    q[2] = __float2bfloat16(a.z * inv); q[3] = __float2bfloat16(a.w * inv);
    q[4] = __float2bfloat16(b.x * inv); q[5] = __float2bfloat16(b.y * inv);
    q[6] = __float2bfloat16(b.z * inv); q[7] = __float2bfloat16(b.w * inv);

    float sd = 0.f;
    #pragma unroll
    for (int k = 0; k < 8; ++k) { float f = __bfloat162float(q[k]); sd += f * f; }
    #pragma unroll
    for (int o = 16; o; o >>= 1) sd += __shfl_xor_sync(0xffffffffu, sd, o);

    uint2* out = reinterpret_cast<uint2*>(g_embn + (size_t)row * DIM);
    __nv_bfloat162 h01, h23, h45, h67;
    h01.x = q[0]; h01.y = q[1]; h23.x = q[2]; h23.y = q[3];
    h45.x = q[4]; h45.y = q[5]; h67.x = q[6]; h67.y = q[7];
    uint2 u0, u1;
    u0.x = *reinterpret_cast<uint32_t*>(&h01); u0.y = *reinterpret_cast<uint32_t*>(&h23);
    u1.x = *reinterpret_cast<uint32_t*>(&h45); u1.y = *reinterpret_cast<uint32_t*>(&h67);
    out[lane]      = u0;
    out[lane + 32] = u1;

    if (lane == 0) g_selfdot[row] = sd;
}

// ---------------------------------------------------------------------------
// Kernel 2: fused GEMM + exp + rowsum. 128 CTAs x 256 threads, 1 CTA/SM.
// smem: A tile 64KB + B double buffer 128KB + 128-float rowsum
// ---------------------------------------------------------------------------
#define SM_A    0
#define SM_B0   65536
#define SM_B1   131072
#define SM_RED  196608
#define SM_TOTAL 197120

extern __shared__ char dyn_smem[];

// stage one 128x256 bf16 tile into swizzled smem (512B rows, SWZ16 on 16B units)
__device__ __forceinline__ void stage_tile(uint32_t sdst, uint64_t gsrc, int tid) {
    int c   = tid & 31;            // 16B column unit, fixed per thread
    int r0  = tid >> 5;            // starting row
    #pragma unroll
    for (int i = 0; i < 16; ++i) {
        int r = r0 + 8 * i;
        uint32_t d = sdst + r * 512 + SWZ16(r, c) * 16;
        cp_async16(d, gsrc + (uint64_t)r * 512 + (uint64_t)c * 16);
    }
}

__global__ void __launch_bounds__(THREADS, 1) contrastive_main_kernel() {
    int tid = threadIdx.x;
    int l   = tid & 31;
    int wid = tid >> 5;
    int wr  = wid >> 2;            // 0..1  (64-row stripe)
    int wc  = wid & 3;             // 0..3  (32-col stripe)
    uint32_t sb = smem_u32(dyn_smem);
    float* srow = reinterpret_cast<float*>(dyn_smem + SM_RED);

    if (tid < 128) srow[tid] = 0.f;

    uint64_t gbase;
    asm("cvta.to.global.u64 %0, %1;" : "=l"(gbase) : "l"((const void*)g_embn));

    // prologue staging: A + B(tile0) as group0, B(tile1) as group1
    stage_tile(sb + SM_A,  gbase + (uint64_t)blockIdx.x * TILE * 512, tid);
    stage_tile(sb + SM_B0, gbase, tid);
    cp_commit();
    stage_tile(sb + SM_B1, gbase + (uint64_t)TILE * 512, tid);
    cp_commit();

    // ldmatrix per-lane address components
    // A map: lanes 0-15 -> rows +0..15 @k0, lanes 16-31 -> rows +0..15 @k0+8
    int la  = l & 15;
    int lha = l >> 4;
    int sa  = la & 7;
    // B map: lanes 0-7 n0-7@k0, 8-15 n0-7@k0+8, 16-23 n8-15@k0, 24-31 n8-15@k0+8
    int lb  = (l & 7) + ((l >> 4) << 3);
    int lhb = (l >> 3) & 1;
    int sbw = lb & 7;

    uint32_t aRow[4], bRow[2];
    #pragma unroll
    for (int mb = 0; mb < 4; ++mb)
        aRow[mb] = sb + SM_A + (uint32_t)(wr * 64 + mb * 16 + la) * 512;
    #pragma unroll
    for (int n2 = 0; n2 < 2; ++n2)
        bRow[n2] = (uint32_t)(wc * 32 + n2 * 16 + lb) * 512;   // add buffer base later

    float acc[4][4][4];
    #pragma unroll
    for (int mb = 0; mb < 4; ++mb)
        #pragma unroll
        for (int nb = 0; nb < 4; ++nb)
            #pragma unroll
            for (int k = 0; k < 4; ++k) acc[mb][nb][k] = 0.f;

    float rowsum[4][2];
    #pragma unroll
    for (int mb = 0; mb < 4; ++mb) { rowsum[mb][0] = 0.f; rowsum[mb][1] = 0.f; }

    for (int j = 0; j < NT; ++j) {
        if (j == NT - 1) asm volatile("cp.async.wait_group 0;" ::: "memory");
        else             asm volatile("cp.async.wait_group 1;" ::: "memory");
        __syncthreads();

        uint32_t bbuf = sb + ((j & 1) ? SM_B1 : SM_B0);

        // ---- k-loop: 16 steps of k=16 ----
        #pragma unroll 4
        for (int ks = 0; ks < 16; ++ks) {
            int cA = 2 * ks + lha;
            int cB = 2 * ks + lhb;
            uint32_t offA = (uint32_t)((((cA ^ sa) & 7) | (cA & 24)) << 4);
            uint32_t offB = (uint32_t)((((cB ^ sbw) & 7) | (cB & 24)) << 4);

            uint32_t afr[4][4];
            #pragma unroll
            for (int mb = 0; mb < 4; ++mb) lm4(aRow[mb] + offA, afr[mb]);
            uint32_t bfr[2][4];
            #pragma unroll
            for (int n2 = 0; n2 < 2; ++n2) lm4(bbuf + bRow[n2] + offB, bfr[n2]);

            #pragma unroll
            for (int mb = 0; mb < 4; ++mb)
                #pragma unroll
                for (int nb = 0; nb < 4; ++nb)
                    mma16816(acc[mb][nb], afr[mb],
                             bfr[nb >> 1][(nb & 1) * 2], bfr[nb >> 1][(nb & 1) * 2 + 1]);
        }
        __syncthreads();   // all warps done reading buffer (j&1)

        // stage tile j+2 into the buffer we just freed (overlaps epilogue below)
        if (j + 2 < NT) {
            stage_tile(sb + ((j & 1) ? SM_B1 : SM_B0),
                       gbase + (uint64_t)(j + 2) * TILE * 512, tid);
            cp_commit();
        }

        // ---- epilogue: exp + row-accumulate, re-zero acc ----
        #pragma unroll
        for (int mb = 0; mb < 4; ++mb) {
            float s0 = 0.f, s1 = 0.f;
            #pragma unroll
            for (int nb = 0; nb < 4; ++nb) {
                s0 += ex2f(fmaf(acc[mb][nb][0], EX2_SCALE, -EX2_SCALE));
                s0 += ex2f(fmaf(acc[mb][nb][1], EX2_SCALE, -EX2_SCALE));
                s1 += ex2f(fmaf(acc[mb][nb][2], EX2_SCALE, -EX2_SCALE));
                s1 += ex2f(fmaf(acc[mb][nb][3], EX2_SCALE, -EX2_SCALE));
                acc[mb][nb][0] = 0.f; acc[mb][nb][1] = 0.f;
                acc[mb][nb][2] = 0.f; acc[mb][nb][3] = 0.f;
            }
            rowsum[mb][0] += s0;
            rowsum[mb][1] += s1;
        }
    }

    // reduce rowsums: lanes sharing (l>>2) hold different columns of the same rows
    #pragma unroll
    for (int mb = 0; mb < 4; ++mb) {
        #pragma unroll
        for (int s = 0; s < 2; ++s) {
            float p = rowsum[mb][s];
            p += __shfl_xor_sync(0xffffffffu, p, 1);
            p += __shfl_xor_sync(0xffffffffu, p, 2);
            if ((l & 3) == 0) {
                int lrow = wr * 64 + mb * 16 + s * 8 + (l >> 2);
                atomicAdd(&srow[lrow], p);
            }
        }
    }
    __syncthreads();

    if (tid < 128) {
        int row = blockIdx.x * TILE + tid;
        float loss = logf(srow[tid]) + (1.0f - g_selfdot[row]) * INV_T;
        #pragma unroll
        for (int o = 16; o; o >>= 1) loss += __shfl_xor_sync(0xffffffffu, loss, o);
        if ((tid & 31) == 0) srow[tid >> 5] = loss;   // reuse srow as scratch
    }
    __syncthreads();
    if (tid == 0) g_partial[blockIdx.x] = (srow[0] + srow[1]) + (srow[2] + srow[3]);
}

// ---------------------------------------------------------------------------
// Kernel 3: final mean over 128 block partials
// ---------------------------------------------------------------------------
__global__ void finalize_kernel(float* __restrict__ out) {
    int t = threadIdx.x;    // 128 threads
    float v = g_partial[t];
    #pragma unroll
    for (int o = 16; o; o >>= 1) v += __shfl_xor_sync(0xffffffffu, v, o);
    __shared__ float r[4];
    if ((t & 31) == 0) r[t >> 5] = v;
    __syncthreads();
    if (t == 0) out[0] = ((r[0] + r[1]) + (r[2] + r[3])) * (1.0f / (float)N_ROWS);
}

// ---------------------------------------------------------------------------
extern "C" void kernel_launch(void* const* d_in, const int* in_sizes, int n_in,
                              void* d_out, int out_size) {
    const float* emb = (const float*)d_in[0];
    float* out = (float*)d_out;
    (void)in_sizes; (void)n_in; (void)out_size;

    cudaFuncSetAttribute(contrastive_main_kernel,
                         cudaFuncAttributeMaxDynamicSharedMemorySize, SM_TOTAL);

    normalize_kernel<<<N_ROWS / 8, 256>>>(emb);
    contrastive_main_kernel<<<NT, THREADS, SM_TOTAL>>>();
    finalize_kernel<<<1, 128>>>(out);
}

// round 4
// speedup vs baseline: 2.6082x; 2.6082x over previous
#include <cuda_runtime.h>
#include <cuda_bf16.h>
#include <cstdint>

// ============================================================================
// ContrastiveLoss: N=16384, D=256, T=0.07
// loss = mean_i [ log(sum_j exp((c_ij - 1)/T)) + (1 - selfdot_i)/T ]
// c_ij = <q_i, q_j>, q = bf16-quantized L2-normalized rows.
// R3: symmetric-tile scheduling — only upper-triangle tiles computed;
// each off-diagonal tile feeds BOTH row sums (rows) and col sums (cols).
// ============================================================================

#define N_ROWS 16384
#define DIM    256
#define TILE   128
#define NT     (N_ROWS / TILE)   // 128
#define THREADS 256

#define INV_T      14.285714285714286f
#define EX2_SCALE  20.60992915555662f   // log2(e)/0.07

__device__ __nv_bfloat16 g_embn[N_ROWS * DIM];   // normalized bf16 rows (512B/row)
__device__ float g_selfdot[N_ROWS];
__device__ float g_rowsum[N_ROWS];               // global exp-row-sum accumulator

// ---------------------------------------------------------------------------
// helpers
// ---------------------------------------------------------------------------
__device__ __forceinline__ uint32_t smem_u32(const void* p) {
    uint32_t a;
    asm("{ .reg .u64 t; cvta.to.shared.u64 t, %1; cvt.u32.u64 %0, t; }" : "=r"(a) : "l"(p));
    return a;
}

__device__ __forceinline__ float ex2f(float x) {
    float y;
    asm("ex2.approx.ftz.f32 %0, %1;" : "=f"(y) : "f"(x));
    return y;
}

#define SWZ16(row, c16) (((((c16) ^ (row)) & 7) | ((c16) & 24)))

__device__ __forceinline__ void lm4(uint32_t addr, uint32_t r[4]) {
    asm volatile("ldmatrix.sync.aligned.m8n8.x4.shared.b16 {%0,%1,%2,%3}, [%4];"
                 : "=r"(r[0]), "=r"(r[1]), "=r"(r[2]), "=r"(r[3]) : "r"(addr));
}

__device__ __forceinline__ void mma16816(float c[4], const uint32_t a[4],
                                         uint32_t b0, uint32_t b1) {
    asm volatile(
        "mma.sync.aligned.m16n8k16.row.col.f32.bf16.bf16.f32 "
        "{%0,%1,%2,%3}, {%4,%5,%6,%7}, {%8,%9}, {%0,%1,%2,%3};"
        : "+f"(c[0]), "+f"(c[1]), "+f"(c[2]), "+f"(c[3])
        : "r"(a[0]), "r"(a[1]), "r"(a[2]), "r"(a[3]), "r"(b0), "r"(b1));
}

__device__ __forceinline__ void cp_async16(uint32_t dst, uint64_t src) {
    asm volatile("cp.async.cg.shared.global [%0], [%1], 16;" :: "r"(dst), "l"(src) : "memory");
}
__device__ __forceinline__ void cp_commit() {
    asm volatile("cp.async.commit_group;" ::: "memory");
}

// ---------------------------------------------------------------------------
// Kernel 1: normalize rows -> bf16, self-dot of quantized row, zero g_rowsum
// ---------------------------------------------------------------------------
__global__ void __launch_bounds__(256) normalize_kernel(const float* __restrict__ in) {
    int row  = blockIdx.x * 8 + (threadIdx.x >> 5);
    int lane = threadIdx.x & 31;

    const float4* p = reinterpret_cast<const float4*>(in + (size_t)row * DIM);
    float4 a = p[lane];
    float4 b = p[lane + 32];

    float s = a.x*a.x + a.y*a.y + a.z*a.z + a.w*a.w
            + b.x*b.x + b.y*b.y + b.z*b.z + b.w*b.w;
    #pragma unroll
    for (int o = 16; o; o >>= 1) s += __shfl_xor_sync(0xffffffffu, s, o);

    float inv = 1.0f / sqrtf(s);

    __nv_bfloat16 q[8];
    q[0] = __float2bfloat16(a.x * inv); q[1] = __float2bfloat16(a.y * inv);
    q[2] = __float2bfloat16(a.z * inv); q[3] = __float2bfloat16(a.w * inv);
    q[4] = __float2bfloat16(b.x * inv); q[5] = __float2bfloat16(b.y * inv);
    q[6] = __float2bfloat16(b.z * inv); q[7] = __float2bfloat16(b.w * inv);

    float sd = 0.f;
    #pragma unroll
    for (int k = 0; k < 8; ++k) { float f = __bfloat162float(q[k]); sd += f * f; }
    #pragma unroll
    for (int o = 16; o; o >>= 1) sd += __shfl_xor_sync(0xffffffffu, sd, o);

    uint2* out = reinterpret_cast<uint2*>(g_embn + (size_t)row * DIM);
    __nv_bfloat162 h01, h23, h45, h67;
    h01.x = q[0]; h01.y = q[1]; h23.x = q[2]; h23.y = q[3];
    h45.x = q[4]; h45.y = q[5]; h67.x = q[6]; h67.y = q[7];
    uint2 u0, u1;
    u0.x = *reinterpret_cast<uint32_t*>(&h01); u0.y = *reinterpret_cast<uint32_t*>(&h23);
    u1.x = *reinterpret_cast<uint32_t*>(&h45); u1.y = *reinterpret_cast<uint32_t*>(&h67);
    out[lane]      = u0;
    out[lane + 32] = u1;

    if (lane == 0) g_selfdot[row] = sd;
    if (lane == 1) g_rowsum[row] = 0.f;   // zero accumulator every launch
}

// ---------------------------------------------------------------------------
// Kernel 2: upper-triangle fused GEMM + exp + row/col sums
// ---------------------------------------------------------------------------
#define SM_A     0
#define SM_B0    65536
#define SM_B1    131072
#define SM_TOTAL 196608

extern __shared__ char dyn_smem[];

__device__ __forceinline__ void stage_tile(uint32_t sdst, uint64_t gsrc, int tid) {
    int c  = tid & 31;
    int r0 = tid >> 5;
    #pragma unroll
    for (int i = 0; i < 16; ++i) {
        int r = r0 + 8 * i;
        uint32_t d = sdst + r * 512 + SWZ16(r, c) * 16;
        cp_async16(d, gsrc + (uint64_t)r * 512 + (uint64_t)c * 16);
    }
}

__global__ void __launch_bounds__(THREADS, 1) contrastive_main_kernel() {
    int bid = blockIdx.x;
    int tid = threadIdx.x;
    int l   = tid & 31;
    int wid = tid >> 5;
    int wr  = wid >> 2;            // 0..1  (64-row stripe)
    int wc  = wid & 3;             // 0..3  (32-col stripe)
    uint32_t sb = smem_u32(dyn_smem);

    uint64_t gbase;
    asm("cvta.to.global.u64 %0, %1;" : "=l"(gbase) : "l"((const void*)g_embn));

    // --- schedule: pair row-block k with 127-k for balance (~64.5 tiles/CTA)
    int runs_I[2], runs_J0[2], runs_cnt[2], nruns;
    if (bid < 64) {
        runs_I[0] = bid; runs_J0[0] = bid; runs_cnt[0] = 65; nruns = 1;
    } else {
        int k = 127 - bid;
        runs_I[0] = k;   runs_J0[0] = k + 65; runs_cnt[0] = 63 - k;
        runs_I[1] = bid; runs_J0[1] = bid;    runs_cnt[1] = 128 - bid;
        nruns = 2;
    }

    // ldmatrix lane maps
    int la  = l & 15;
    int lha = l >> 4;
    int sa  = la & 7;
    int lb  = (l & 7) + ((l >> 4) << 3);
    int lhb = (l >> 3) & 1;
    int sbw = lb & 7;

    uint32_t aRow[4], bRow[2];
    #pragma unroll
    for (int mb = 0; mb < 4; ++mb)
        aRow[mb] = sb + SM_A + (uint32_t)(wr * 64 + mb * 16 + la) * 512;
    #pragma unroll
    for (int n2 = 0; n2 < 2; ++n2)
        bRow[n2] = (uint32_t)(wc * 32 + n2 * 16 + lb) * 512;

    float acc[4][4][4];
    #pragma unroll
    for (int mb = 0; mb < 4; ++mb)
        #pragma unroll
        for (int nb = 0; nb < 4; ++nb)
            #pragma unroll
            for (int k = 0; k < 4; ++k) acc[mb][nb][k] = 0.f;

    for (int r = 0; r < nruns; ++r) {
        int I     = runs_I[r];
        int Jbase = runs_J0[r];
        int cnt   = runs_cnt[r];
        if (cnt <= 0) continue;

        // prologue staging for this run: A + B0 (group), B1 (group)
        stage_tile(sb + SM_A,  gbase + (uint64_t)I * TILE * 512, tid);
        stage_tile(sb + SM_B0, gbase + (uint64_t)Jbase * TILE * 512, tid);
        cp_commit();
        if (cnt > 1) {
            stage_tile(sb + SM_B1, gbase + (uint64_t)(Jbase + 1) * TILE * 512, tid);
            cp_commit();
        }

        float rowsum[4][2];
        #pragma unroll
        for (int mb = 0; mb < 4; ++mb) { rowsum[mb][0] = 0.f; rowsum[mb][1] = 0.f; }

        for (int t = 0; t < cnt; ++t) {
            if (t == cnt - 1) asm volatile("cp.async.wait_group 0;" ::: "memory");
            else              asm volatile("cp.async.wait_group 1;" ::: "memory");
            __syncthreads();

            uint32_t bbuf = sb + ((t & 1) ? SM_B1 : SM_B0);

            // ---- k-loop: 16 steps of k=16 ----
            #pragma unroll 4
            for (int ks = 0; ks < 16; ++ks) {
                int cA = 2 * ks + lha;
                int cB = 2 * ks + lhb;
                uint32_t offA = (uint32_t)((((cA ^ sa) & 7) | (cA & 24)) << 4);
                uint32_t offB = (uint32_t)((((cB ^ sbw) & 7) | (cB & 24)) << 4);

                uint32_t afr[4][4];
                #pragma unroll
                for (int mb = 0; mb < 4; ++mb) lm4(aRow[mb] + offA, afr[mb]);
                uint32_t bfr[2][4];
                #pragma unroll
                for (int n2 = 0; n2 < 2; ++n2) lm4(bbuf + bRow[n2] + offB, bfr[n2]);

                #pragma unroll
                for (int mb = 0; mb < 4; ++mb)
                    #pragma unroll
                    for (int nb = 0; nb < 4; ++nb)
                        mma16816(acc[mb][nb], afr[mb],
                                 bfr[nb >> 1][(nb & 1) * 2], bfr[nb >> 1][(nb & 1) * 2 + 1]);
            }
            __syncthreads();   // done reading this B buffer

            // stage tile t+2 into freed buffer (overlaps epilogue)
            if (t + 2 < cnt) {
                stage_tile(sb + ((t & 1) ? SM_B1 : SM_B0),
                           gbase + (uint64_t)(Jbase + t + 2) * TILE * 512, tid);
                cp_commit();
            }

            int J    = Jbase + t;
            bool diag = (J == I);

            // ---- epilogue: exp, row sums (regs) + col sums (shuffle+REDG) ----
            float cv0[4] = {0.f, 0.f, 0.f, 0.f};
            float cv1[4] = {0.f, 0.f, 0.f, 0.f};
            #pragma unroll
            for (int mb = 0; mb < 4; ++mb) {
                float s0 = 0.f, s1 = 0.f;
                #pragma unroll
                for (int nb = 0; nb < 4; ++nb) {
                    float e0 = ex2f(fmaf(acc[mb][nb][0], EX2_SCALE, -EX2_SCALE));
                    float e1 = ex2f(fmaf(acc[mb][nb][1], EX2_SCALE, -EX2_SCALE));
                    float e2 = ex2f(fmaf(acc[mb][nb][2], EX2_SCALE, -EX2_SCALE));
                    float e3 = ex2f(fmaf(acc[mb][nb][3], EX2_SCALE, -EX2_SCALE));
                    s0 += e0 + e1;
                    s1 += e2 + e3;
                    cv0[nb] += e0 + e2;
                    cv1[nb] += e1 + e3;
                    acc[mb][nb][0] = 0.f; acc[mb][nb][1] = 0.f;
                    acc[mb][nb][2] = 0.f; acc[mb][nb][3] = 0.f;
                }
                rowsum[mb][0] += s0;
                rowsum[mb][1] += s1;
            }

            if (!diag) {
                // column sums -> g_rowsum[J*128 + col]
                #pragma unroll
                for (int nb = 0; nb < 4; ++nb) {
                    float v0 = cv0[nb], v1 = cv1[nb];
                    v0 += __shfl_xor_sync(0xffffffffu, v0, 4);
                    v1 += __shfl_xor_sync(0xffffffffu, v1, 4);
                    v0 += __shfl_xor_sync(0xffffffffu, v0, 8);
                    v1 += __shfl_xor_sync(0xffffffffu, v1, 8);
                    v0 += __shfl_xor_sync(0xffffffffu, v0, 16);
                    v1 += __shfl_xor_sync(0xffffffffu, v1, 16);
                    if (l < 4) {
                        int col = J * TILE + wc * 32 + nb * 8 + 2 * l;
                        atomicAdd(&g_rowsum[col],     v0);
                        atomicAdd(&g_rowsum[col + 1], v1);
                    }
                }
            }
        }

        // ---- flush register row sums for this run's I block ----
        #pragma unroll
        for (int mb = 0; mb < 4; ++mb) {
            #pragma unroll
            for (int s = 0; s < 2; ++s) {
                float p = rowsum[mb][s];
                p += __shfl_xor_sync(0xffffffffu, p, 1);
                p += __shfl_xor_sync(0xffffffffu, p, 2);
                if ((l & 3) == 0) {
                    int row = I * TILE + wr * 64 + mb * 16 + s * 8 + (l >> 2);
                    atomicAdd(&g_rowsum[row], p);
                }
            }
        }
        __syncthreads();   // all reads of A done before next run restages it
    }
}

// ---------------------------------------------------------------------------
// Kernel 3: loss_i = log(rowsum_i) + (1 - selfdot_i)/T;  out = mean
// ---------------------------------------------------------------------------
__global__ void __launch_bounds__(1024) finalize_kernel(float* __restrict__ out) {
    int t = threadIdx.x;
    float acc = 0.f;
    #pragma unroll
    for (int i = 0; i < 16; ++i) {
        int r = t + i * 1024;
        acc += logf(g_rowsum[r]) + (1.0f - g_selfdot[r]) * INV_T;
    }
    #pragma unroll
    for (int o = 16; o; o >>= 1) acc += __shfl_xor_sync(0xffffffffu, acc, o);
    __shared__ float red[32];
    if ((t & 31) == 0) red[t >> 5] = acc;
    __syncthreads();
    if (t < 32) {
        float v = red[t];
        #pragma unroll
        for (int o = 16; o; o >>= 1) v += __shfl_xor_sync(0xffffffffu, v, o);
        if (t == 0) out[0] = v * (1.0f / (float)N_ROWS);
    }
}

// ---------------------------------------------------------------------------
extern "C" void kernel_launch(void* const* d_in, const int* in_sizes, int n_in,
                              void* d_out, int out_size) {
    const float* emb = (const float*)d_in[0];
    float* out = (float*)d_out;
    (void)in_sizes; (void)n_in; (void)out_size;

    cudaFuncSetAttribute(contrastive_main_kernel,
                         cudaFuncAttributeMaxDynamicSharedMemorySize, SM_TOTAL);

    normalize_kernel<<<N_ROWS / 8, 256>>>(emb);
    contrastive_main_kernel<<<NT, THREADS, SM_TOTAL>>>();
    finalize_kernel<<<1, 1024>>>(out);
}

// round 5
// speedup vs baseline: 3.2599x; 1.2499x over previous
#include <cuda_runtime.h>
#include <cuda_bf16.h>
#include <cstdint>

// ============================================================================
// ContrastiveLoss: N=16384, D=256, T=0.07
// loss = mean_i [ log(sum_j exp((c_ij - 1)/T)) + (1 - selfdot_i)/T ]
// R5: 148-CTA persistent triangle scheduler (paired row order) +
//     software-pipelined exp epilogue interleaved into the MMA mainloop.
// ============================================================================

#define N_ROWS 16384
#define DIM    256
#define TILE   128
#define NT     (N_ROWS / TILE)   // 128
#define THREADS 256
#define GRID   148
#define TOTAL_TILES (NT * (NT + 1) / 2)   // 8256

#define INV_T      14.285714285714286f
#define EX2_SCALE  20.60992915555662f   // log2(e)/0.07

__device__ __nv_bfloat16 g_embn[N_ROWS * DIM];   // normalized bf16 rows (512B/row)
__device__ float g_selfdot[N_ROWS];
__device__ float g_rowsum[N_ROWS];

// ---------------------------------------------------------------------------
__device__ __forceinline__ uint32_t smem_u32(const void* p) {
    uint32_t a;
    asm("{ .reg .u64 t; cvta.to.shared.u64 t, %1; cvt.u32.u64 %0, t; }" : "=r"(a) : "l"(p));
    return a;
}

__device__ __forceinline__ float ex2f(float x) {
    float y;
    asm("ex2.approx.ftz.f32 %0, %1;" : "=f"(y) : "f"(x));
    return y;
}

#define SWZ16(row, c16) (((((c16) ^ (row)) & 7) | ((c16) & 24)))

__device__ __forceinline__ void lm4(uint32_t addr, uint32_t r[4]) {
    asm volatile("ldmatrix.sync.aligned.m8n8.x4.shared.b16 {%0,%1,%2,%3}, [%4];"
                 : "=r"(r[0]), "=r"(r[1]), "=r"(r[2]), "=r"(r[3]) : "r"(addr));
}

__device__ __forceinline__ void mma16816(float c[4], const uint32_t a[4],
                                         uint32_t b0, uint32_t b1) {
    asm volatile(
        "mma.sync.aligned.m16n8k16.row.col.f32.bf16.bf16.f32 "
        "{%0,%1,%2,%3}, {%4,%5,%6,%7}, {%8,%9}, {%0,%1,%2,%3};"
        : "+f"(c[0]), "+f"(c[1]), "+f"(c[2]), "+f"(c[3])
        : "r"(a[0]), "r"(a[1]), "r"(a[2]), "r"(a[3]), "r"(b0), "r"(b1));
}

__device__ __forceinline__ void cp_async16(uint32_t dst, uint64_t src) {
    asm volatile("cp.async.cg.shared.global [%0], [%1], 16;" :: "r"(dst), "l"(src) : "memory");
}
__device__ __forceinline__ void cp_commit() {
    asm volatile("cp.async.commit_group;" ::: "memory");
}

// ---------------------------------------------------------------------------
// Kernel 1: normalize rows -> bf16, self-dot of quantized row, zero g_rowsum
// ---------------------------------------------------------------------------
__global__ void __launch_bounds__(256) normalize_kernel(const float* __restrict__ in) {
    int row  = blockIdx.x * 8 + (threadIdx.x >> 5);
    int lane = threadIdx.x & 31;

    const float4* p = reinterpret_cast<const float4*>(in + (size_t)row * DIM);
    float4 a = p[lane];
    float4 b = p[lane + 32];

    float s = a.x*a.x + a.y*a.y + a.z*a.z + a.w*a.w
            + b.x*b.x + b.y*b.y + b.z*b.z + b.w*b.w;
    #pragma unroll
    for (int o = 16; o; o >>= 1) s += __shfl_xor_sync(0xffffffffu, s, o);

    float inv = 1.0f / sqrtf(s);

    __nv_bfloat16 q[8];
    q[0] = __float2bfloat16(a.x * inv); q[1] = __float2bfloat16(a.y * inv);
    q[2] = __float2bfloat16(a.z * inv); q[3] = __float2bfloat16(a.w * inv);
    q[4] = __float2bfloat16(b.x * inv); q[5] = __float2bfloat16(b.y * inv);
    q[6] = __float2bfloat16(b.z * inv); q[7] = __float2bfloat16(b.w * inv);

    float sd = 0.f;
    #pragma unroll
    for (int k = 0; k < 8; ++k) { float f = __bfloat162float(q[k]); sd += f * f; }
    #pragma unroll
    for (int o = 16; o; o >>= 1) sd += __shfl_xor_sync(0xffffffffu, sd, o);

    uint2* out = reinterpret_cast<uint2*>(g_embn + (size_t)row * DIM);
    __nv_bfloat162 h01, h23, h45, h67;
    h01.x = q[0]; h01.y = q[1]; h23.x = q[2]; h23.y = q[3];
    h45.x = q[4]; h45.y = q[5]; h67.x = q[6]; h67.y = q[7];
    uint2 u0, u1;
    u0.x = *reinterpret_cast<uint32_t*>(&h01); u0.y = *reinterpret_cast<uint32_t*>(&h23);
    u1.x = *reinterpret_cast<uint32_t*>(&h45); u1.y = *reinterpret_cast<uint32_t*>(&h67);
    out[lane]      = u0;
    out[lane + 32] = u1;

    if (lane == 0) g_selfdot[row] = sd;
    if (lane == 1) g_rowsum[row] = 0.f;
}

// ---------------------------------------------------------------------------
// Kernel 2: upper-triangle fused GEMM + exp + row/col sums (persistent, 148 CTAs)
// ---------------------------------------------------------------------------
#define SM_A     0
#define SM_B0    65536
#define SM_B1    131072
#define SM_TOTAL 196608

extern __shared__ char dyn_smem[];

__device__ __forceinline__ void stage_tile(uint32_t sdst, uint64_t gsrc, int tid) {
    int c  = tid & 31;
    int r0 = tid >> 5;
    #pragma unroll
    for (int i = 0; i < 16; ++i) {
        int r = r0 + 8 * i;
        uint32_t d = sdst + r * 512 + SWZ16(r, c) * 16;
        cp_async16(d, gsrc + (uint64_t)r * 512 + (uint64_t)c * 16);
    }
}

// one tile's 16 k-steps; optionally interleave exp-epilogue of prev tile
template<bool EPI>
__device__ __forceinline__ void tile_step(
    uint32_t bbuf, const uint32_t aRow[4], const uint32_t bRow[2],
    int lha, int lhb, int sa, int sbw,
    float acc[4][4][4], float prev[4][4][4],
    float rowsum[4][2], float cv0[4], float cv1[4])
{
    #pragma unroll
    for (int ks = 0; ks < 16; ++ks) {
        int cA = 2 * ks + lha;
        int cB = 2 * ks + lhb;
        uint32_t offA = (uint32_t)((((cA ^ sa) & 7) | (cA & 24)) << 4);
        uint32_t offB = (uint32_t)((((cB ^ sbw) & 7) | (cB & 24)) << 4);

        uint32_t afr[4][4];
        #pragma unroll
        for (int mb = 0; mb < 4; ++mb) lm4(aRow[mb] + offA, afr[mb]);
        uint32_t bfr[2][4];
        #pragma unroll
        for (int n2 = 0; n2 < 2; ++n2) lm4(bbuf + bRow[n2] + offB, bfr[n2]);

        #pragma unroll
        for (int mb = 0; mb < 4; ++mb)
            #pragma unroll
            for (int nb = 0; nb < 4; ++nb)
                mma16816(acc[mb][nb], afr[mb],
                         bfr[nb >> 1][(nb & 1) * 2], bfr[nb >> 1][(nb & 1) * 2 + 1]);

        if (EPI) {
            // 4 exps of prev tile per k-step (16 steps cover all 64 values)
            const int mb = ks >> 2, nb = ks & 3;
            float e0 = ex2f(fmaf(prev[mb][nb][0], EX2_SCALE, -EX2_SCALE));
            float e1 = ex2f(fmaf(prev[mb][nb][1], EX2_SCALE, -EX2_SCALE));
            float e2 = ex2f(fmaf(prev[mb][nb][2], EX2_SCALE, -EX2_SCALE));
            float e3 = ex2f(fmaf(prev[mb][nb][3], EX2_SCALE, -EX2_SCALE));
            rowsum[mb][0] += e0 + e1;
            rowsum[mb][1] += e2 + e3;
            cv0[nb] += e0 + e2;
            cv1[nb] += e1 + e3;
        }
    }
}

// column-sum flush for tile J (off-diagonal): shuffle-reduce + global atomic
__device__ __forceinline__ void flush_cols(float cv0[4], float cv1[4],
                                           int J, int wc, int l) {
    #pragma unroll
    for (int nb = 0; nb < 4; ++nb) {
        float v0 = cv0[nb], v1 = cv1[nb];
        v0 += __shfl_xor_sync(0xffffffffu, v0, 4);
        v1 += __shfl_xor_sync(0xffffffffu, v1, 4);
        v0 += __shfl_xor_sync(0xffffffffu, v0, 8);
        v1 += __shfl_xor_sync(0xffffffffu, v1, 8);
        v0 += __shfl_xor_sync(0xffffffffu, v0, 16);
        v1 += __shfl_xor_sync(0xffffffffu, v1, 16);
        if (l < 4) {
            int col = J * TILE + wc * 32 + nb * 8 + 2 * l;
            atomicAdd(&g_rowsum[col],     v0);
            atomicAdd(&g_rowsum[col + 1], v1);
        }
        cv0[nb] = 0.f; cv1[nb] = 0.f;
    }
}

__global__ void __launch_bounds__(THREADS, 1) contrastive_main_kernel() {
    int bid = blockIdx.x;
    int tid = threadIdx.x;
    int l   = tid & 31;
    int wid = tid >> 5;
    int wr  = wid >> 2;
    int wc  = wid & 3;
    uint32_t sb = smem_u32(dyn_smem);

    uint64_t gbase;
    asm("cvta.to.global.u64 %0, %1;" : "=l"(gbase) : "l"((const void*)g_embn));

    // ldmatrix lane maps
    int la  = l & 15;
    int lha = l >> 4;
    int sa  = la & 7;
    int lb  = (l & 7) + ((l >> 4) << 3);
    int lhb = (l >> 3) & 1;
    int sbw = lb & 7;

    uint32_t aRow[4], bRow[2];
    #pragma unroll
    for (int mb = 0; mb < 4; ++mb)
        aRow[mb] = sb + SM_A + (uint32_t)(wr * 64 + mb * 16 + la) * 512;
    #pragma unroll
    for (int n2 = 0; n2 < 2; ++n2)
        bRow[n2] = (uint32_t)(wc * 32 + n2 * 16 + lb) * 512;

    float acc[4][4][4], prev[4][4][4];
    #pragma unroll
    for (int mb = 0; mb < 4; ++mb)
        #pragma unroll
        for (int nb = 0; nb < 4; ++nb)
            #pragma unroll
            for (int k = 0; k < 4; ++k) { acc[mb][nb][k] = 0.f; prev[mb][nb][k] = 0.f; }

    float cv0[4] = {0,0,0,0}, cv1[4] = {0,0,0,0};

    // --- persistent scheduler: linearized triangle, paired row order ---
    int start = (int)(((long long)bid       * TOTAL_TILES) / GRID);
    int end   = (int)(((long long)(bid + 1) * TOTAL_TILES) / GRID);

    int s = 0, I = 0, cum = 0;
    for (;; ++s) {
        I = (s & 1) ? (NT - 1 - (s >> 1)) : (s >> 1);
        int rowlen = NT - I;
        if (cum + rowlen > start) break;
        cum += rowlen;
    }
    int J0  = I + (start - cum);
    int idx = start;

    while (idx < end) {
        int cnt = min(end - idx, NT - J0);

        // --- stage A + first B tiles for this run ---
        stage_tile(sb + SM_A,  gbase + (uint64_t)I * TILE * 512, tid);
        stage_tile(sb + SM_B0, gbase + (uint64_t)J0 * TILE * 512, tid);
        cp_commit();
        if (cnt > 1) {
            stage_tile(sb + SM_B1, gbase + (uint64_t)(J0 + 1) * TILE * 512, tid);
            cp_commit();
        }

        float rowsum[4][2];
        #pragma unroll
        for (int mb = 0; mb < 4; ++mb) { rowsum[mb][0] = 0.f; rowsum[mb][1] = 0.f; }

        int Jprev = -1;

        for (int t = 0; t < cnt; ++t) {
            if (t == cnt - 1) asm volatile("cp.async.wait_group 0;" ::: "memory");
            else              asm volatile("cp.async.wait_group 1;" ::: "memory");
            __syncthreads();

            uint32_t bbuf = sb + ((t & 1) ? SM_B1 : SM_B0);

            if (t == 0)
                tile_step<false>(bbuf, aRow, bRow, lha, lhb, sa, sbw,
                                 acc, prev, rowsum, cv0, cv1);
            else
                tile_step<true>(bbuf, aRow, bRow, lha, lhb, sa, sbw,
                                acc, prev, rowsum, cv0, cv1);
            __syncthreads();   // all warps done reading this B buffer

            if (t + 2 < cnt) {
                stage_tile(sb + ((t & 1) ? SM_B1 : SM_B0),
                           gbase + (uint64_t)(J0 + t + 2) * TILE * 512, tid);
                cp_commit();
            }

            // finish prev tile: flush its column sums (skip diagonal)
            if (t > 0) {
                if (Jprev != I) flush_cols(cv0, cv1, Jprev, wc, l);
                else { cv0[0]=cv0[1]=cv0[2]=cv0[3]=0.f; cv1[0]=cv1[1]=cv1[2]=cv1[3]=0.f; }
            }

            // rotate: acc -> prev, zero acc
            #pragma unroll
            for (int mb = 0; mb < 4; ++mb)
                #pragma unroll
                for (int nb = 0; nb < 4; ++nb)
                    #pragma unroll
                    for (int k = 0; k < 4; ++k) {
                        prev[mb][nb][k] = acc[mb][nb][k];
                        acc[mb][nb][k]  = 0.f;
                    }
            Jprev = J0 + t;
        }

        // --- drain: epilogue of the run's final tile ---
        #pragma unroll
        for (int mb = 0; mb < 4; ++mb)
            #pragma unroll
            for (int nb = 0; nb < 4; ++nb) {
                float e0 = ex2f(fmaf(prev[mb][nb][0], EX2_SCALE, -EX2_SCALE));
                float e1 = ex2f(fmaf(prev[mb][nb][1], EX2_SCALE, -EX2_SCALE));
                float e2 = ex2f(fmaf(prev[mb][nb][2], EX2_SCALE, -EX2_SCALE));
                float e3 = ex2f(fmaf(prev[mb][nb][3], EX2_SCALE, -EX2_SCALE));
                rowsum[mb][0] += e0 + e1;
                rowsum[mb][1] += e2 + e3;
                cv0[nb] += e0 + e2;
                cv1[nb] += e1 + e3;
                prev[mb][nb][0] = 0.f; prev[mb][nb][1] = 0.f;
                prev[mb][nb][2] = 0.f; prev[mb][nb][3] = 0.f;
            }
        if (Jprev != I) flush_cols(cv0, cv1, Jprev, wc, l);
        else { cv0[0]=cv0[1]=cv0[2]=cv0[3]=0.f; cv1[0]=cv1[1]=cv1[2]=cv1[3]=0.f; }

        // --- flush row sums for this run's I block ---
        #pragma unroll
        for (int mb = 0; mb < 4; ++mb) {
            #pragma unroll
            for (int ss = 0; ss < 2; ++ss) {
                float p = rowsum[mb][ss];
                p += __shfl_xor_sync(0xffffffffu, p, 1);
                p += __shfl_xor_sync(0xffffffffu, p, 2);
                if ((l & 3) == 0) {
                    int row = I * TILE + wr * 64 + mb * 16 + ss * 8 + (l >> 2);
                    atomicAdd(&g_rowsum[row], p);
                }
            }
        }

        // advance to next row in paired order
        idx += cnt;
        ++s;
        I  = (s & 1) ? (NT - 1 - (s >> 1)) : (s >> 1);
        J0 = I;
    }
}

// ---------------------------------------------------------------------------
// Kernel 3: loss_i = log(rowsum_i) + (1 - selfdot_i)/T;  out = mean
// ---------------------------------------------------------------------------
__global__ void __launch_bounds__(1024) finalize_kernel(float* __restrict__ out) {
    int t = threadIdx.x;
    float acc = 0.f;
    #pragma unroll
    for (int i = 0; i < 16; ++i) {
        int r = t + i * 1024;
        acc += logf(g_rowsum[r]) + (1.0f - g_selfdot[r]) * INV_T;
    }
    #pragma unroll
    for (int o = 16; o; o >>= 1) acc += __shfl_xor_sync(0xffffffffu, acc, o);
    __shared__ float red[32];
    if ((t & 31) == 0) red[t >> 5] = acc;
    __syncthreads();
    if (t < 32) {
        float v = red[t];
        #pragma unroll
        for (int o = 16; o; o >>= 1) v += __shfl_xor_sync(0xffffffffu, v, o);
        if (t == 0) out[0] = v * (1.0f / (float)N_ROWS);
    }
}

// ---------------------------------------------------------------------------
extern "C" void kernel_launch(void* const* d_in, const int* in_sizes, int n_in,
                              void* d_out, int out_size) {
    const float* emb = (const float*)d_in[0];
    float* out = (float*)d_out;
    (void)in_sizes; (void)n_in; (void)out_size;

    cudaFuncSetAttribute(contrastive_main_kernel,
                         cudaFuncAttributeMaxDynamicSharedMemorySize, SM_TOTAL);

    normalize_kernel<<<N_ROWS / 8, 256>>>(emb);
    contrastive_main_kernel<<<GRID, THREADS, SM_TOTAL>>>();
    finalize_kernel<<<1, 1024>>>(out);
}